// round 4
// baseline (speedup 1.0000x reference)
#include <cuda_runtime.h>
#include <cuda_bf16.h>

#define HW 256
#define PLANE (HW * HW)
#define TILE 4
#define NT 256
#define NLD 224              // loader threads (warps 1..7)
#define SQS 292              // float4 stride of one step-row in smem

// Per-(plane,dir) scratch, plane index = bc*4 + dir.
// dirs 0,1 (horizontal) stored TRANSPOSED [w][h]; dirs 2,3 natural [h][w].
__device__ float g_scratch[512 * PLANE];

// k -> conflict-free smem slot within a step-row (lane = k>>3 owns 8 slots at 9*lane)
__device__ __forceinline__ int kmap(int k) { return 9 * (k >> 3) + (k & 7); }

__device__ __forceinline__ float4 gate_pack(float m, float g1, float g2, float g3) {
    float s = fabsf(g1) + fabsf(g2) + fabsf(g3) + 1e-7f;
    float r = (s >= 1.f) ? __fdividef(1.f, s) : 1.f;
    float a = g1 * r, b = g2 * r, c = g3 * r;
    return make_float4((1.f - a - b - c) * m, a, b, c);
}

__global__ __launch_bounds__(NT) void spn_scan(
    const float* __restrict__ x,
    const float* __restrict__ mask)
{
    extern __shared__ float4 sq[];         // [2][TILE][SQS] {p,a,b,c}

    const int tid = threadIdx.x;
    const int blk = blockIdx.x;
    const int dir = blk & 3;               // interleave dirs -> mask L2 reuse
    const int bc  = blk >> 2;
    const int b   = bc >> 5;
    const int c   = bc & 31;
    const bool horiz = (dir < 2);
    const bool rev   = (dir & 1);
    const int NTILES = HW / TILE;          // 64

    const float* mb  = mask + (size_t)bc * PLANE;
    const float* g1b = x + (size_t)(b * 384 + (3 * dir + 0) * 32 + c) * PLANE;
    const float* g2b = x + (size_t)(b * 384 + (3 * dir + 1) * 32 + c) * PLANE;
    const float* g3b = x + (size_t)(b * 384 + (3 * dir + 2) * 32 + c) * PLANE;
    float* scr = g_scratch + (size_t)blk * PLANE;

    const int lane = tid & 31;

    // ---------- loader lambda-ish macro via inline code ----------
    // Loads tile tt (0..NTILES-1) into buffer bufp. Called by threads 32..255.
    // groups: 256 per tile, each = 4 elements along the fast dim (float4 LDG).
    //   horiz: group g = k; elements are 4 consecutive steps (w).
    //   vert : group g -> L = g>>6, k4 = g&63; elements are 4 consecutive k.

    // ---------- prologue: load tile 0 ----------
    if (tid >= 32) {
        int tt = 0;
        int base0 = rev ? (HW - TILE) : 0;
        float4* bufp = sq;                 // buffer 0
        int g = tid - 32;
        #pragma unroll
        for (int rep = 0; rep < 2; ++rep, g += NLD) {
            if (g < 256) {
                if (horiz) {
                    int k = g;
                    int ga = k * HW + base0;
                    float4 M = *(const float4*)(mb  + ga);
                    float4 A = *(const float4*)(g1b + ga);
                    float4 B = *(const float4*)(g2b + ga);
                    float4 C = *(const float4*)(g3b + ga);
                    int km = kmap(k);
                    bufp[0 * SQS + km] = gate_pack(M.x, A.x, B.x, C.x);
                    bufp[1 * SQS + km] = gate_pack(M.y, A.y, B.y, C.y);
                    bufp[2 * SQS + km] = gate_pack(M.z, A.z, B.z, C.z);
                    bufp[3 * SQS + km] = gate_pack(M.w, A.w, B.w, C.w);
                } else {
                    int L = g >> 6, k4 = g & 63;
                    int ga = (base0 + L) * HW + 4 * k4;
                    float4 M = *(const float4*)(mb  + ga);
                    float4 A = *(const float4*)(g1b + ga);
                    float4 B = *(const float4*)(g2b + ga);
                    float4 C = *(const float4*)(g3b + ga);
                    float4* row = bufp + L * SQS;
                    row[kmap(4 * k4 + 0)] = gate_pack(M.x, A.x, B.x, C.x);
                    row[kmap(4 * k4 + 1)] = gate_pack(M.y, A.y, B.y, C.y);
                    row[kmap(4 * k4 + 2)] = gate_pack(M.z, A.z, B.z, C.z);
                    row[kmap(4 * k4 + 3)] = gate_pack(M.w, A.w, B.w, C.w);
                }
            }
        }
        (void)tt;
    }
    float h[8];
    #pragma unroll
    for (int e = 0; e < 8; ++e) h[e] = 0.f;
    __syncthreads();

    // ---------- main loop: scan tile t || load tile t+1 ----------
    for (int t = 0; t < NTILES; ++t) {
        if (tid < 32) {
            // ---- scanner: warp 0, whole 256-wide k-line, zero barriers ----
            const float4* buf = sq + (size_t)(t & 1) * (TILE * SQS);
            const int base0 = rev ? (HW - TILE - TILE * t) : (TILE * t);
            #pragma unroll
            for (int st = 0; st < TILE; ++st) {
                int L = rev ? (TILE - 1 - st) : st;
                const float4* row = buf + L * SQS + 9 * lane;
                float4 q0 = row[0], q1 = row[1], q2 = row[2], q3 = row[3];
                float4 q4 = row[4], q5 = row[5], q6 = row[6], q7 = row[7];
                float hm = __shfl_up_sync(0xffffffffu, h[7], 1);
                float hp = __shfl_down_sync(0xffffffffu, h[0], 1);
                if (lane == 0)  hm = 0.f;
                if (lane == 31) hp = 0.f;
                float hn[8];
                hn[0] = fmaf(q0.w, h[1], fmaf(q0.z, h[0], fmaf(q0.y, hm,   q0.x)));
                hn[1] = fmaf(q1.w, h[2], fmaf(q1.z, h[1], fmaf(q1.y, h[0], q1.x)));
                hn[2] = fmaf(q2.w, h[3], fmaf(q2.z, h[2], fmaf(q2.y, h[1], q2.x)));
                hn[3] = fmaf(q3.w, h[4], fmaf(q3.z, h[3], fmaf(q3.y, h[2], q3.x)));
                hn[4] = fmaf(q4.w, h[5], fmaf(q4.z, h[4], fmaf(q4.y, h[3], q4.x)));
                hn[5] = fmaf(q5.w, h[6], fmaf(q5.z, h[5], fmaf(q5.y, h[4], q5.x)));
                hn[6] = fmaf(q6.w, h[7], fmaf(q6.z, h[6], fmaf(q6.y, h[5], q6.x)));
                hn[7] = fmaf(q7.w, hp,   fmaf(q7.z, h[7], fmaf(q7.y, h[6], q7.x)));
                #pragma unroll
                for (int e = 0; e < 8; ++e) h[e] = hn[e];
                // direct coalesced store: 256 consecutive floats per step
                float* orow = scr + (base0 + L) * HW + 8 * lane;
                *(float4*)(orow)     = make_float4(h[0], h[1], h[2], h[3]);
                *(float4*)(orow + 4) = make_float4(h[4], h[5], h[6], h[7]);
            }
        } else if (t + 1 < NTILES) {
            // ---- loaders: warps 1..7 fetch + normalize tile t+1 ----
            const int base0 = rev ? (HW - TILE - TILE * (t + 1)) : (TILE * (t + 1));
            float4* bufp = sq + (size_t)((t + 1) & 1) * (TILE * SQS);
            int g = tid - 32;
            #pragma unroll
            for (int rep = 0; rep < 2; ++rep, g += NLD) {
                if (g < 256) {
                    if (horiz) {
                        int k = g;
                        int ga = k * HW + base0;
                        float4 M = *(const float4*)(mb  + ga);
                        float4 A = *(const float4*)(g1b + ga);
                        float4 B = *(const float4*)(g2b + ga);
                        float4 C = *(const float4*)(g3b + ga);
                        int km = kmap(k);
                        bufp[0 * SQS + km] = gate_pack(M.x, A.x, B.x, C.x);
                        bufp[1 * SQS + km] = gate_pack(M.y, A.y, B.y, C.y);
                        bufp[2 * SQS + km] = gate_pack(M.z, A.z, B.z, C.z);
                        bufp[3 * SQS + km] = gate_pack(M.w, A.w, B.w, C.w);
                    } else {
                        int L = g >> 6, k4 = g & 63;
                        int ga = (base0 + L) * HW + 4 * k4;
                        float4 M = *(const float4*)(mb  + ga);
                        float4 A = *(const float4*)(g1b + ga);
                        float4 B = *(const float4*)(g2b + ga);
                        float4 C = *(const float4*)(g3b + ga);
                        float4* row = bufp + L * SQS;
                        row[kmap(4 * k4 + 0)] = gate_pack(M.x, A.x, B.x, C.x);
                        row[kmap(4 * k4 + 1)] = gate_pack(M.y, A.y, B.y, C.y);
                        row[kmap(4 * k4 + 2)] = gate_pack(M.z, A.z, B.z, C.z);
                        row[kmap(4 * k4 + 3)] = gate_pack(M.w, A.w, B.w, C.w);
                    }
                }
            }
        }
        __syncthreads();
    }
}

// out(h,w) = max over 4 dirs; dirs 0,1 transposed in scratch.
// Tile 32x32; ALL gmem accesses are float4.
__global__ __launch_bounds__(256) void spn_max(float* __restrict__ out)
{
    __shared__ float t0[32][33], t1[32][33];
    const int bc   = blockIdx.x >> 6;
    const int tile = blockIdx.x & 63;
    const int h0 = (tile >> 3) * 32, w0 = (tile & 7) * 32;
    const int r = threadIdx.x >> 3;        // 0..31
    const int q = threadIdx.x & 7;         // 0..7
    const float* S = g_scratch + (size_t)bc * 4 * PLANE;

    // load transposed planes: row = w, contiguous in h -> float4 along h
    {
        int w = w0 + r;
        float4 v0 = *(const float4*)(S + 0 * PLANE + w * HW + h0 + 4 * q);
        float4 v1 = *(const float4*)(S + 1 * PLANE + w * HW + h0 + 4 * q);
        t0[r][4 * q + 0] = v0.x; t0[r][4 * q + 1] = v0.y;
        t0[r][4 * q + 2] = v0.z; t0[r][4 * q + 3] = v0.w;
        t1[r][4 * q + 0] = v1.x; t1[r][4 * q + 1] = v1.y;
        t1[r][4 * q + 2] = v1.z; t1[r][4 * q + 3] = v1.w;
    }
    __syncthreads();

    int h = h0 + r;
    int gbase = h * HW + w0 + 4 * q;
    float4 a = *(const float4*)(S + 2 * PLANE + gbase);
    float4 bb = *(const float4*)(S + 3 * PLANE + gbase);
    float4 v;
    v.x = fmaxf(fmaxf(a.x, bb.x), fmaxf(t0[4 * q + 0][r], t1[4 * q + 0][r]));
    v.y = fmaxf(fmaxf(a.y, bb.y), fmaxf(t0[4 * q + 1][r], t1[4 * q + 1][r]));
    v.z = fmaxf(fmaxf(a.z, bb.z), fmaxf(t0[4 * q + 2][r], t1[4 * q + 2][r]));
    v.w = fmaxf(fmaxf(a.w, bb.w), fmaxf(t0[4 * q + 3][r], t1[4 * q + 3][r]));
    *(float4*)(out + (size_t)bc * PLANE + gbase) = v;
}

extern "C" void kernel_launch(void* const* d_in, const int* in_sizes, int n_in,
                              void* d_out, int out_size) {
    const float* x    = (const float*)d_in[0];
    const float* mask = (const float*)d_in[1];
    if (n_in >= 2 && in_sizes[0] < in_sizes[1]) {   // defensive: x is 12x mask
        x    = (const float*)d_in[1];
        mask = (const float*)d_in[0];
    }
    size_t smem = (size_t)(2 * TILE * SQS) * sizeof(float4);  // 37,376 B
    spn_scan<<<512, NT, smem>>>(x, mask);
    spn_max<<<128 * 64, 256>>>((float*)d_out);
}

// round 5
// speedup vs baseline: 1.0548x; 1.0548x over previous
#include <cuda_runtime.h>
#include <cuda_bf16.h>

#define HW 256
#define PLANE (HW * HW)
#define TILE 8
#define NT 256
#define NLD 224              // loader threads (warps 1..7)
#define NGRP 512             // float4 groups per tile (TILE*HW/4)
#define SQS 293              // float4 stride of one step-row (odd => no cross-row STS conflict)

// Per-(plane,dir) scratch, plane index = bc*4 + dir.
// dirs 0,1 (horizontal) stored TRANSPOSED [w][h]; dirs 2,3 natural [h][w].
__device__ float g_scratch[512 * PLANE];

// k -> conflict-free smem slot within a step-row (lane = k>>3 owns 8 slots at 9*lane)
__device__ __forceinline__ int kmap(int k) { return 9 * (k >> 3) + (k & 7); }

__device__ __forceinline__ float4 gate_pack(float m, float g1, float g2, float g3) {
    float s = fabsf(g1) + fabsf(g2) + fabsf(g3) + 1e-7f;
    float r = (s >= 1.f) ? __fdividef(1.f, s) : 1.f;
    float a = g1 * r, b = g2 * r, c = g3 * r;
    return make_float4((1.f - a - b - c) * m, a, b, c);
}

// Loaders (threads 32..255): fetch + normalize one 8-step tile into buf.
// Sector-exact: horizontal rows fetch 32B (8 steps) via 2 float4 groups.
__device__ __forceinline__ void load_tile(
    float4* buf, int base0, bool horiz, int tid,
    const float* __restrict__ mb, const float* __restrict__ g1b,
    const float* __restrict__ g2b, const float* __restrict__ g3b)
{
    for (int g = tid - 32; g < NGRP; g += NLD) {
        int ga, L0, kbase;          // L of element j = L0 + j*dL ; k of element j = kbase + j*dk
        if (horiz) {
            int k = g >> 1, hf = g & 1;
            ga = k * HW + base0 + 4 * hf;
            float4 M = *(const float4*)(mb  + ga);
            float4 A = *(const float4*)(g1b + ga);
            float4 B = *(const float4*)(g2b + ga);
            float4 C = *(const float4*)(g3b + ga);
            int km = kmap(k);
            L0 = 4 * hf;
            buf[(L0 + 0) * SQS + km] = gate_pack(M.x, A.x, B.x, C.x);
            buf[(L0 + 1) * SQS + km] = gate_pack(M.y, A.y, B.y, C.y);
            buf[(L0 + 2) * SQS + km] = gate_pack(M.z, A.z, B.z, C.z);
            buf[(L0 + 3) * SQS + km] = gate_pack(M.w, A.w, B.w, C.w);
        } else {
            int L = g >> 6, k4 = g & 63;
            ga = (base0 + L) * HW + 4 * k4;
            float4 M = *(const float4*)(mb  + ga);
            float4 A = *(const float4*)(g1b + ga);
            float4 B = *(const float4*)(g2b + ga);
            float4 C = *(const float4*)(g3b + ga);
            kbase = 4 * k4;
            float4* row = buf + L * SQS;
            row[kmap(kbase + 0)] = gate_pack(M.x, A.x, B.x, C.x);
            row[kmap(kbase + 1)] = gate_pack(M.y, A.y, B.y, C.y);
            row[kmap(kbase + 2)] = gate_pack(M.z, A.z, B.z, C.z);
            row[kmap(kbase + 3)] = gate_pack(M.w, A.w, B.w, C.w);
        }
        (void)L0; (void)kbase; (void)ga;
    }
}

__global__ __launch_bounds__(NT, 3) void spn_scan(
    const float* __restrict__ x,
    const float* __restrict__ mask)
{
    extern __shared__ float4 sq[];         // [2][TILE][SQS] packed {p,a,b,c}

    const int tid = threadIdx.x;
    const int blk = blockIdx.x;
    const int dir = blk & 3;               // interleave dirs -> mask L2 reuse
    const int bc  = blk >> 2;
    const int b   = bc >> 5;
    const int c   = bc & 31;
    const bool horiz = (dir < 2);
    const bool rev   = (dir & 1);
    const int NTILES = HW / TILE;          // 32

    const float* mb  = mask + (size_t)bc * PLANE;
    const float* g1b = x + (size_t)(b * 384 + (3 * dir + 0) * 32 + c) * PLANE;
    const float* g2b = x + (size_t)(b * 384 + (3 * dir + 1) * 32 + c) * PLANE;
    const float* g3b = x + (size_t)(b * 384 + (3 * dir + 2) * 32 + c) * PLANE;
    float* scr = g_scratch + (size_t)blk * PLANE;

    const int lane = tid & 31;

    // ---- prologue: loaders fill buffer 0 with tile 0 ----
    if (tid >= 32)
        load_tile(sq, rev ? (HW - TILE) : 0, horiz, tid, mb, g1b, g2b, g3b);

    float h[8];
    #pragma unroll
    for (int e = 0; e < 8; ++e) h[e] = 0.f;
    __syncthreads();

    // ---- main loop: warp 0 scans tile t, warps 1..7 load tile t+1 ----
    for (int t = 0; t < NTILES; ++t) {
        if (tid < 32) {
            const float4* buf = sq + (size_t)(t & 1) * (TILE * SQS);
            const int base0 = rev ? (HW - TILE - TILE * t) : (TILE * t);
            #pragma unroll
            for (int st = 0; st < TILE; ++st) {
                int L = rev ? (TILE - 1 - st) : st;
                const float4* row = buf + L * SQS + 9 * lane;
                float4 q0 = row[0], q1 = row[1], q2 = row[2], q3 = row[3];
                float4 q4 = row[4], q5 = row[5], q6 = row[6], q7 = row[7];
                float hm = __shfl_up_sync(0xffffffffu, h[7], 1);
                float hp = __shfl_down_sync(0xffffffffu, h[0], 1);
                if (lane == 0)  hm = 0.f;
                if (lane == 31) hp = 0.f;
                float hn[8];
                hn[0] = fmaf(q0.w, h[1], fmaf(q0.z, h[0], fmaf(q0.y, hm,   q0.x)));
                hn[1] = fmaf(q1.w, h[2], fmaf(q1.z, h[1], fmaf(q1.y, h[0], q1.x)));
                hn[2] = fmaf(q2.w, h[3], fmaf(q2.z, h[2], fmaf(q2.y, h[1], q2.x)));
                hn[3] = fmaf(q3.w, h[4], fmaf(q3.z, h[3], fmaf(q3.y, h[2], q3.x)));
                hn[4] = fmaf(q4.w, h[5], fmaf(q4.z, h[4], fmaf(q4.y, h[3], q4.x)));
                hn[5] = fmaf(q5.w, h[6], fmaf(q5.z, h[5], fmaf(q5.y, h[4], q5.x)));
                hn[6] = fmaf(q6.w, h[7], fmaf(q6.z, h[6], fmaf(q6.y, h[5], q6.x)));
                hn[7] = fmaf(q7.w, hp,   fmaf(q7.z, h[7], fmaf(q7.y, h[6], q7.x)));
                #pragma unroll
                for (int e = 0; e < 8; ++e) h[e] = hn[e];
                float* orow = scr + (base0 + L) * HW + 8 * lane;
                *(float4*)(orow)     = make_float4(h[0], h[1], h[2], h[3]);
                *(float4*)(orow + 4) = make_float4(h[4], h[5], h[6], h[7]);
            }
        } else if (t + 1 < NTILES) {
            float4* bufn = sq + (size_t)((t + 1) & 1) * (TILE * SQS);
            int base0 = rev ? (HW - TILE - TILE * (t + 1)) : (TILE * (t + 1));
            load_tile(bufn, base0, horiz, tid, mb, g1b, g2b, g3b);
        }
        __syncthreads();
    }
}

// out(h,w) = max over 4 dirs; dirs 0,1 transposed in scratch.
// Tile 32x32; ALL gmem accesses are float4.
__global__ __launch_bounds__(256) void spn_max(float* __restrict__ out)
{
    __shared__ float t0[32][33], t1[32][33];
    const int bc   = blockIdx.x >> 6;
    const int tile = blockIdx.x & 63;
    const int h0 = (tile >> 3) * 32, w0 = (tile & 7) * 32;
    const int r = threadIdx.x >> 3;        // 0..31
    const int q = threadIdx.x & 7;         // 0..7
    const float* S = g_scratch + (size_t)bc * 4 * PLANE;

    {
        int w = w0 + r;
        float4 v0 = *(const float4*)(S + 0 * PLANE + w * HW + h0 + 4 * q);
        float4 v1 = *(const float4*)(S + 1 * PLANE + w * HW + h0 + 4 * q);
        t0[r][4 * q + 0] = v0.x; t0[r][4 * q + 1] = v0.y;
        t0[r][4 * q + 2] = v0.z; t0[r][4 * q + 3] = v0.w;
        t1[r][4 * q + 0] = v1.x; t1[r][4 * q + 1] = v1.y;
        t1[r][4 * q + 2] = v1.z; t1[r][4 * q + 3] = v1.w;
    }
    __syncthreads();

    int h = h0 + r;
    int gbase = h * HW + w0 + 4 * q;
    float4 a  = *(const float4*)(S + 2 * PLANE + gbase);
    float4 bb = *(const float4*)(S + 3 * PLANE + gbase);
    float4 v;
    v.x = fmaxf(fmaxf(a.x, bb.x), fmaxf(t0[4 * q + 0][r], t1[4 * q + 0][r]));
    v.y = fmaxf(fmaxf(a.y, bb.y), fmaxf(t0[4 * q + 1][r], t1[4 * q + 1][r]));
    v.z = fmaxf(fmaxf(a.z, bb.z), fmaxf(t0[4 * q + 2][r], t1[4 * q + 2][r]));
    v.w = fmaxf(fmaxf(a.w, bb.w), fmaxf(t0[4 * q + 3][r], t1[4 * q + 3][r]));
    *(float4*)(out + (size_t)bc * PLANE + gbase) = v;
}

extern "C" void kernel_launch(void* const* d_in, const int* in_sizes, int n_in,
                              void* d_out, int out_size) {
    const float* x    = (const float*)d_in[0];
    const float* mask = (const float*)d_in[1];
    if (n_in >= 2 && in_sizes[0] < in_sizes[1]) {   // defensive: x is 12x mask
        x    = (const float*)d_in[1];
        mask = (const float*)d_in[0];
    }
    size_t smem = (size_t)(2 * TILE * SQS) * sizeof(float4);  // 75,008 B
    cudaFuncSetAttribute(spn_scan, cudaFuncAttributeMaxDynamicSharedMemorySize, (int)smem);
    spn_scan<<<512, NT, smem>>>(x, mask);
    spn_max<<<128 * 64, 256>>>((float*)d_out);
}

// round 6
// speedup vs baseline: 1.3452x; 1.2753x over previous
#include <cuda_runtime.h>
#include <cuda_bf16.h>

#define HW 256
#define PLANE (HW * HW)
#define TILE 8
#define NT 288               // 9 warps: warp0 = scanner, warps 1..8 = 256 loaders
#define NLDR 256
#define SQS 293              // float4 row stride (odd => 4-row STS phase conflict-free)

// Per-(plane,dir) scratch, plane index = bc*4 + dir.
// dirs 0,1 (horizontal) stored TRANSPOSED [w][h]; dirs 2,3 natural [h][w].
__device__ float g_scratch[512 * PLANE];

// k -> conflict-free smem slot within a step-row (lane = k>>3 owns slots 9*lane..+7)
__device__ __forceinline__ int kmap(int k) { return 9 * (k >> 3) + (k & 7); }

__device__ __forceinline__ float4 gate_pack(float m, float g1, float g2, float g3) {
    float s = fabsf(g1) + fabsf(g2) + fabsf(g3) + 1e-7f;
    float r = (s >= 1.f) ? __fdividef(1.f, s) : 1.f;
    float a = g1 * r, b = g2 * r, c = g3 * r;
    return make_float4((1.f - a - b - c) * m, a, b, c);
}

struct Stage { float4 M[2], A[2], B[2], C[2]; };

// Fully unrolled: 8 independent LDG.128s, front-batched by ptxas (high MLP).
__device__ __forceinline__ void ldg_tile(Stage& s, int base0, bool horiz, int lt,
    const float* __restrict__ mb, const float* __restrict__ g1b,
    const float* __restrict__ g2b, const float* __restrict__ g3b)
{
    #pragma unroll
    for (int i = 0; i < 2; ++i) {
        int g = lt + i * NLDR;
        int ga;
        if (horiz) { int k = g >> 1, hf = g & 1;  ga = k * HW + base0 + 4 * hf; }
        else       { int L = g >> 6, k4 = g & 63; ga = (base0 + L) * HW + 4 * k4; }
        s.M[i] = *(const float4*)(mb  + ga);
        s.A[i] = *(const float4*)(g1b + ga);
        s.B[i] = *(const float4*)(g2b + ga);
        s.C[i] = *(const float4*)(g3b + ga);
    }
}

__device__ __forceinline__ void sts_tile(const Stage& s, float4* buf, bool horiz, int lt)
{
    #pragma unroll
    for (int i = 0; i < 2; ++i) {
        int g = lt + i * NLDR;
        const float* Mp = (const float*)&s.M[i];
        const float* Ap = (const float*)&s.A[i];
        const float* Bp = (const float*)&s.B[i];
        const float* Cp = (const float*)&s.C[i];
        if (horiz) {
            int k = g >> 1, hf = g & 1;
            int km = kmap(k), L0 = 4 * hf;
            #pragma unroll
            for (int j = 0; j < 4; ++j)
                buf[(L0 + j) * SQS + km] = gate_pack(Mp[j], Ap[j], Bp[j], Cp[j]);
        } else {
            int L = g >> 6, k4 = g & 63;
            float4* row = buf + L * SQS;
            #pragma unroll
            for (int j = 0; j < 4; ++j)
                row[kmap(4 * k4 + j)] = gate_pack(Mp[j], Ap[j], Bp[j], Cp[j]);
        }
    }
}

__global__ __launch_bounds__(NT, 3) void spn_scan(
    const float* __restrict__ x,
    const float* __restrict__ mask)
{
    extern __shared__ float4 sq[];         // single buffer [TILE][SQS] {p,a,b,c}

    const int tid = threadIdx.x;
    const int blk = blockIdx.x;
    const int dir = blk & 3;               // interleave dirs -> mask L2 reuse
    const int bc  = blk >> 2;
    const int b   = bc >> 5;
    const int c   = bc & 31;
    const bool horiz = (dir < 2);
    const bool rev   = (dir & 1);
    const int NTILES = HW / TILE;          // 32

    const float* mb  = mask + (size_t)bc * PLANE;
    const float* g1b = x + (size_t)(b * 384 + (3 * dir + 0) * 32 + c) * PLANE;
    const float* g2b = x + (size_t)(b * 384 + (3 * dir + 1) * 32 + c) * PLANE;
    const float* g3b = x + (size_t)(b * 384 + (3 * dir + 2) * 32 + c) * PLANE;
    float* scr = g_scratch + (size_t)blk * PLANE;

    const int lane = tid & 31;
    const int lt   = tid - 32;             // loader id 0..255

    // ---- prologue: loaders fetch + pack tile 0 ----
    if (tid >= 32) {
        Stage s;
        ldg_tile(s, rev ? (HW - TILE) : 0, horiz, lt, mb, g1b, g2b, g3b);
        sts_tile(s, sq, horiz, lt);
    }
    float h[8];
    #pragma unroll
    for (int e = 0; e < 8; ++e) h[e] = 0.f;
    __syncthreads();

    for (int t = 0; t < NTILES; ++t) {
        Stage s;
        if (tid < 32) {
            // ---- scanner: warp 0, whole 256-wide k-line, zero barriers ----
            const int base0 = rev ? (HW - TILE - TILE * t) : (TILE * t);
            #pragma unroll
            for (int st = 0; st < TILE; ++st) {
                int L = rev ? (TILE - 1 - st) : st;
                const float4* row = sq + L * SQS + 9 * lane;
                float4 q0 = row[0], q1 = row[1], q2 = row[2], q3 = row[3];
                float4 q4 = row[4], q5 = row[5], q6 = row[6], q7 = row[7];
                float hm = __shfl_up_sync(0xffffffffu, h[7], 1);
                float hp = __shfl_down_sync(0xffffffffu, h[0], 1);
                if (lane == 0)  hm = 0.f;
                if (lane == 31) hp = 0.f;
                float hn[8];
                hn[0] = fmaf(q0.w, h[1], fmaf(q0.z, h[0], fmaf(q0.y, hm,   q0.x)));
                hn[1] = fmaf(q1.w, h[2], fmaf(q1.z, h[1], fmaf(q1.y, h[0], q1.x)));
                hn[2] = fmaf(q2.w, h[3], fmaf(q2.z, h[2], fmaf(q2.y, h[1], q2.x)));
                hn[3] = fmaf(q3.w, h[4], fmaf(q3.z, h[3], fmaf(q3.y, h[2], q3.x)));
                hn[4] = fmaf(q4.w, h[5], fmaf(q4.z, h[4], fmaf(q4.y, h[3], q4.x)));
                hn[5] = fmaf(q5.w, h[6], fmaf(q5.z, h[5], fmaf(q5.y, h[4], q5.x)));
                hn[6] = fmaf(q6.w, h[7], fmaf(q6.z, h[6], fmaf(q6.y, h[5], q6.x)));
                hn[7] = fmaf(q7.w, hp,   fmaf(q7.z, h[7], fmaf(q7.y, h[6], q7.x)));
                #pragma unroll
                for (int e = 0; e < 8; ++e) h[e] = hn[e];
                float* orow = scr + (base0 + L) * HW + 8 * lane;
                *(float4*)(orow)     = make_float4(h[0], h[1], h[2], h[3]);
                *(float4*)(orow + 4) = make_float4(h[4], h[5], h[6], h[7]);
            }
        } else if (t + 1 < NTILES) {
            // ---- loaders: issue next tile's LDGs (no wait before barrier) ----
            int base0 = rev ? (HW - TILE - TILE * (t + 1)) : (TILE * (t + 1));
            ldg_tile(s, base0, horiz, lt, mb, g1b, g2b, g3b);
        }
        __syncthreads();                   // scanner done reading sq
        if (tid >= 32 && t + 1 < NTILES)
            sts_tile(s, sq, horiz, lt);    // drain scoreboard, normalize, pack
        __syncthreads();                   // sq ready for next scan
    }
}

// out(h,w) = max over 4 dirs; dirs 0,1 transposed in scratch.
// Tile 32x32; ALL gmem accesses are float4.
__global__ __launch_bounds__(256) void spn_max(float* __restrict__ out)
{
    __shared__ float t0[32][33], t1[32][33];
    const int bc   = blockIdx.x >> 6;
    const int tile = blockIdx.x & 63;
    const int h0 = (tile >> 3) * 32, w0 = (tile & 7) * 32;
    const int r = threadIdx.x >> 3;        // 0..31
    const int q = threadIdx.x & 7;         // 0..7
    const float* S = g_scratch + (size_t)bc * 4 * PLANE;

    {
        int w = w0 + r;
        float4 v0 = *(const float4*)(S + 0 * PLANE + w * HW + h0 + 4 * q);
        float4 v1 = *(const float4*)(S + 1 * PLANE + w * HW + h0 + 4 * q);
        t0[r][4 * q + 0] = v0.x; t0[r][4 * q + 1] = v0.y;
        t0[r][4 * q + 2] = v0.z; t0[r][4 * q + 3] = v0.w;
        t1[r][4 * q + 0] = v1.x; t1[r][4 * q + 1] = v1.y;
        t1[r][4 * q + 2] = v1.z; t1[r][4 * q + 3] = v1.w;
    }
    __syncthreads();

    int h = h0 + r;
    int gbase = h * HW + w0 + 4 * q;
    float4 a  = *(const float4*)(S + 2 * PLANE + gbase);
    float4 bb = *(const float4*)(S + 3 * PLANE + gbase);
    float4 v;
    v.x = fmaxf(fmaxf(a.x, bb.x), fmaxf(t0[4 * q + 0][r], t1[4 * q + 0][r]));
    v.y = fmaxf(fmaxf(a.y, bb.y), fmaxf(t0[4 * q + 1][r], t1[4 * q + 1][r]));
    v.z = fmaxf(fmaxf(a.z, bb.z), fmaxf(t0[4 * q + 2][r], t1[4 * q + 2][r]));
    v.w = fmaxf(fmaxf(a.w, bb.w), fmaxf(t0[4 * q + 3][r], t1[4 * q + 3][r]));
    *(float4*)(out + (size_t)bc * PLANE + gbase) = v;
}

extern "C" void kernel_launch(void* const* d_in, const int* in_sizes, int n_in,
                              void* d_out, int out_size) {
    const float* x    = (const float*)d_in[0];
    const float* mask = (const float*)d_in[1];
    if (n_in >= 2 && in_sizes[0] < in_sizes[1]) {   // defensive: x is 12x mask
        x    = (const float*)d_in[1];
        mask = (const float*)d_in[0];
    }
    size_t smem = (size_t)(TILE * SQS) * sizeof(float4);  // 37,504 B
    spn_scan<<<512, NT, smem>>>(x, mask);
    spn_max<<<128 * 64, 256>>>((float*)d_out);
}

// round 8
// speedup vs baseline: 1.5562x; 1.1569x over previous
#include <cuda_runtime.h>
#include <cuda_bf16.h>
#include <cstdint>

#define HW 256
#define PLANE (HW * HW)
#define TILE 8
#define NT 288               // warp0 = scanner; warps 1..8 = 256 loaders
#define SQS 293              // packed float4 row stride (odd => STS conflict-free)
#define RING 2
#define NTILES (HW / TILE)   // 32

// Per-(plane,dir) scratch, plane index = bc*4 + dir.
// dirs 0,1 (horizontal) stored TRANSPOSED [w][h]; dirs 2,3 natural [h][w].
__device__ float g_scratch[512 * PLANE];

// k -> conflict-free smem slot within a packed step-row
__device__ __forceinline__ int kmap(int k) { return 9 * (k >> 3) + (k & 7); }

__device__ __forceinline__ float4 gate_pack(float m, float g1, float g2, float g3) {
    float s = fabsf(g1) + fabsf(g2) + fabsf(g3) + 1e-7f;
    float r = (s >= 1.f) ? __fdividef(1.f, s) : 1.f;
    float a = g1 * r, b = g2 * r, c = g3 * r;
    return make_float4((1.f - a - b - c) * m, a, b, c);
}

__device__ __forceinline__ void cp16(unsigned int dst, const float* src) {
    asm volatile("cp.async.cg.shared.global [%0], [%1], 16;\n" :: "r"(dst), "l"(src));
}
#define CP_COMMIT() asm volatile("cp.async.commit_group;\n" ::: "memory")
#define CP_WAIT1()  asm volatile("cp.async.wait_group 1;\n" ::: "memory")

// Issue one tile's 16B chunks into ring slot (loader lt: 2 chunks x 4 arrays).
__device__ __forceinline__ void issue_tile(
    unsigned int raw_u32, int slot, int base0, bool horiz, int lt,
    const float* __restrict__ mb, const float* __restrict__ g1b,
    const float* __restrict__ g2b, const float* __restrict__ g3b)
{
    #pragma unroll
    for (int i = 0; i < 2; ++i) {
        int g = lt + i * 256;
        int ga;
        if (horiz) { int k = g >> 1, hf = g & 1;  ga = k * HW + base0 + 4 * hf; }
        else       { int L = g >> 6, k4 = g & 63; ga = (base0 + L) * HW + 4 * k4; }
        unsigned int d = raw_u32 + (unsigned int)slot * 32768u + (unsigned int)g * 16u;
        cp16(d,          mb  + ga);
        cp16(d +  8192u, g1b + ga);
        cp16(d + 16384u, g2b + ga);
        cp16(d + 24576u, g3b + ga);
    }
}

// Repack one tile from raw ring slot into the packed buffer (own chunks only).
__device__ __forceinline__ void repack_tile(
    const float4* __restrict__ raw, float4* __restrict__ packed, bool horiz, int lt)
{
    #pragma unroll
    for (int i = 0; i < 2; ++i) {
        int g = lt + i * 256;
        float4 M = raw[0 * 512 + g];
        float4 A = raw[1 * 512 + g];
        float4 B = raw[2 * 512 + g];
        float4 C = raw[3 * 512 + g];
        const float* Mp = (const float*)&M;
        const float* Ap = (const float*)&A;
        const float* Bp = (const float*)&B;
        const float* Cp = (const float*)&C;
        if (horiz) {
            int k = g >> 1, hf = g & 1;
            int km = kmap(k), L0 = 4 * hf;
            #pragma unroll
            for (int j = 0; j < 4; ++j)
                packed[(L0 + j) * SQS + km] = gate_pack(Mp[j], Ap[j], Bp[j], Cp[j]);
        } else {
            int L = g >> 6, k4 = g & 63;
            float4* row = packed + L * SQS;
            #pragma unroll
            for (int j = 0; j < 4; ++j)
                row[kmap(4 * k4 + j)] = gate_pack(Mp[j], Ap[j], Bp[j], Cp[j]);
        }
    }
}

__global__ __launch_bounds__(NT, 2) void spn_scan(
    const float* __restrict__ x,
    const float* __restrict__ mask)
{
    extern __shared__ float4 smem4[];
    float4* packed = smem4;                            // [TILE][SQS] {p,a,b,c}
    float4* raw    = smem4 + TILE * SQS;               // ring: [RING][4][512] float4
    unsigned int raw_u32 = (unsigned int)__cvta_generic_to_shared(raw);

    const int tid = threadIdx.x;
    const int blk = blockIdx.x;
    const int dir = blk & 3;                           // interleave dirs -> mask L2 reuse
    const int bc  = blk >> 2;
    const int b   = bc >> 5;
    const int c   = bc & 31;
    const bool horiz = (dir < 2);
    const bool rev   = (dir & 1);

    const float* mb  = mask + (size_t)bc * PLANE;
    const float* g1b = x + (size_t)(b * 384 + (3 * dir + 0) * 32 + c) * PLANE;
    const float* g2b = x + (size_t)(b * 384 + (3 * dir + 1) * 32 + c) * PLANE;
    const float* g3b = x + (size_t)(b * 384 + (3 * dir + 2) * 32 + c) * PLANE;
    float* scr = g_scratch + (size_t)blk * PLANE;

    const int lane = tid & 31;
    const int lt   = tid - 32;                         // loader id 0..255 (scanner: -32..-1)

    auto tbase = [&](int t) { return rev ? (HW - TILE - TILE * t) : (TILE * t); };

    // ---- prologue: fill pipeline (tiles 0,1 in flight), repack tile 0 ----
    if (lt >= 0) {
        issue_tile(raw_u32, 0, tbase(0), horiz, lt, mb, g1b, g2b, g3b);
        CP_COMMIT();
        issue_tile(raw_u32, 1, tbase(1), horiz, lt, mb, g1b, g2b, g3b);
        CP_COMMIT();
        CP_WAIT1();                                    // tile 0 complete
        repack_tile(raw, packed, horiz, lt);
    }
    float h[8];
    #pragma unroll
    for (int e = 0; e < 8; ++e) h[e] = 0.f;
    __syncthreads();

    for (int t = 0; t < NTILES; ++t) {
        if (tid < 32) {
            // ---- phase A: scanner, whole 256-wide k-line, zero barriers ----
            const int base0 = tbase(t);
            #pragma unroll
            for (int st = 0; st < TILE; ++st) {
                int L = rev ? (TILE - 1 - st) : st;
                const float4* row = packed + L * SQS + 9 * lane;
                float4 q0 = row[0], q1 = row[1], q2 = row[2], q3 = row[3];
                float4 q4 = row[4], q5 = row[5], q6 = row[6], q7 = row[7];
                float hm = __shfl_up_sync(0xffffffffu, h[7], 1);
                float hp = __shfl_down_sync(0xffffffffu, h[0], 1);
                if (lane == 0)  hm = 0.f;
                if (lane == 31) hp = 0.f;
                float hn[8];
                hn[0] = fmaf(q0.w, h[1], fmaf(q0.z, h[0], fmaf(q0.y, hm,   q0.x)));
                hn[1] = fmaf(q1.w, h[2], fmaf(q1.z, h[1], fmaf(q1.y, h[0], q1.x)));
                hn[2] = fmaf(q2.w, h[3], fmaf(q2.z, h[2], fmaf(q2.y, h[1], q2.x)));
                hn[3] = fmaf(q3.w, h[4], fmaf(q3.z, h[3], fmaf(q3.y, h[2], q3.x)));
                hn[4] = fmaf(q4.w, h[5], fmaf(q4.z, h[4], fmaf(q4.y, h[3], q4.x)));
                hn[5] = fmaf(q5.w, h[6], fmaf(q5.z, h[5], fmaf(q5.y, h[4], q5.x)));
                hn[6] = fmaf(q6.w, h[7], fmaf(q6.z, h[6], fmaf(q6.y, h[5], q6.x)));
                hn[7] = fmaf(q7.w, hp,   fmaf(q7.z, h[7], fmaf(q7.y, h[6], q7.x)));
                #pragma unroll
                for (int e = 0; e < 8; ++e) h[e] = hn[e];
                float* orow = scr + (base0 + L) * HW + 8 * lane;
                *(float4*)(orow)     = make_float4(h[0], h[1], h[2], h[3]);
                *(float4*)(orow + 4) = make_float4(h[4], h[5], h[6], h[7]);
            }
        } else {
            // ---- phase A (loaders): issue tile t+2 under the scan ----
            if (t + 2 < NTILES)
                issue_tile(raw_u32, (t + 2) & 1, tbase(t + 2), horiz, lt,
                           mb, g1b, g2b, g3b);
            CP_COMMIT();                               // always commit (group bookkeeping)
        }
        __syncthreads();                               // scanner done with packed(t)

        // ---- phase B: wait tile t+1 data, repack raw -> packed ----
        if (lt >= 0 && t + 1 < NTILES) {
            CP_WAIT1();                                // allow newest 1 group pending
            repack_tile(raw + (size_t)((t + 1) & 1) * 2048, packed, horiz, lt);
        }
        __syncthreads();                               // packed(t+1) ready
    }
}

// out(h,w) = max over 4 dirs; dirs 0,1 transposed in scratch. All gmem float4.
__global__ __launch_bounds__(256) void spn_max(float* __restrict__ out)
{
    __shared__ float t0[32][33], t1[32][33];
    const int bc   = blockIdx.x >> 6;
    const int tile = blockIdx.x & 63;
    const int h0 = (tile >> 3) * 32, w0 = (tile & 7) * 32;
    const int r = threadIdx.x >> 3;
    const int q = threadIdx.x & 7;
    const float* S = g_scratch + (size_t)bc * 4 * PLANE;

    {
        int w = w0 + r;
        float4 v0 = *(const float4*)(S + 0 * PLANE + w * HW + h0 + 4 * q);
        float4 v1 = *(const float4*)(S + 1 * PLANE + w * HW + h0 + 4 * q);
        t0[r][4 * q + 0] = v0.x; t0[r][4 * q + 1] = v0.y;
        t0[r][4 * q + 2] = v0.z; t0[r][4 * q + 3] = v0.w;
        t1[r][4 * q + 0] = v1.x; t1[r][4 * q + 1] = v1.y;
        t1[r][4 * q + 2] = v1.z; t1[r][4 * q + 3] = v1.w;
    }
    __syncthreads();

    int h = h0 + r;
    int gbase = h * HW + w0 + 4 * q;
    float4 a  = *(const float4*)(S + 2 * PLANE + gbase);
    float4 bb = *(const float4*)(S + 3 * PLANE + gbase);
    float4 v;
    v.x = fmaxf(fmaxf(a.x, bb.x), fmaxf(t0[4 * q + 0][r], t1[4 * q + 0][r]));
    v.y = fmaxf(fmaxf(a.y, bb.y), fmaxf(t0[4 * q + 1][r], t1[4 * q + 1][r]));
    v.z = fmaxf(fmaxf(a.z, bb.z), fmaxf(t0[4 * q + 2][r], t1[4 * q + 2][r]));
    v.w = fmaxf(fmaxf(a.w, bb.w), fmaxf(t0[4 * q + 3][r], t1[4 * q + 3][r]));
    *(float4*)(out + (size_t)bc * PLANE + gbase) = v;
}

extern "C" void kernel_launch(void* const* d_in, const int* in_sizes, int n_in,
                              void* d_out, int out_size) {
    const float* x    = (const float*)d_in[0];
    const float* mask = (const float*)d_in[1];
    if (n_in >= 2 && in_sizes[0] < in_sizes[1]) {   // defensive: x is 12x mask
        x    = (const float*)d_in[1];
        mask = (const float*)d_in[0];
    }
    size_t smem = (size_t)TILE * SQS * sizeof(float4)        // packed 37,504 B
                + (size_t)RING * 4 * 2048 * sizeof(float);   // raw ring 65,536 B
    cudaFuncSetAttribute(spn_scan, cudaFuncAttributeMaxDynamicSharedMemorySize, (int)smem);
    spn_scan<<<512, NT, smem>>>(x, mask);
    spn_max<<<128 * 64, 256>>>((float*)d_out);
}